// round 3
// baseline (speedup 1.0000x reference)
#include <cuda_runtime.h>

#define THREADS 256
#define TILE_E  128
#define KD1 312          // xdup row floats: 144 dup-pairs (288) + swizzle headroom (24)
#define HP  68           // h row floats: 64 + pad
#define KD2 152          // x2dup row floats: 64 dup-pairs (128) + swizzle headroom (24)

// float offsets in dynamic smem
#define OFF_W1 0                 // 144*64 = 9216
#define OFF_W2 9216              // 64*64  = 4096
#define OFF_P  13312             // 7*64 = 448 params
#define OFF_X  13760             // xdup: 128*312 = 39936 floats
#define SMEM_FLOATS (OFF_X + TILE_E*KD1)   // 53696 floats = 214784 bytes

typedef unsigned long long ull;

__device__ __forceinline__ ull ffma2(ull a, ull b, ull c) {
    ull d;
    asm("fma.rn.f32x2 %0, %1, %2, %3;" : "=l"(d) : "l"(a), "l"(b), "l"(c));
    return d;
}
__device__ __forceinline__ ull ld64s(const float* p) {
    return *(const ull*)p;
}
__device__ __forceinline__ float2 u2f2(ull u) {
    float2 f;
    asm("mov.b64 {%0, %1}, %2;" : "=f"(f.x), "=f"(f.y) : "l"(u));
    return f;
}
// store float4 v duplicated as 8 floats: x,x,y,y,z,z,w,w
__device__ __forceinline__ void st_dup(float* p, float4 v) {
    *(float4*)(p)     = make_float4(v.x, v.x, v.y, v.y);
    *(float4*)(p + 4) = make_float4(v.z, v.z, v.w, v.w);
}

__global__ __launch_bounds__(THREADS)
void edge_mlp_kernel(const float* __restrict__ nf,
                     const int* __restrict__ eidx,      // int32 (JAX x64 disabled)
                     const float* __restrict__ eattr,
                     const float* __restrict__ W1, const float* __restrict__ b1,
                     const float* __restrict__ g1, const float* __restrict__ be1,
                     const float* __restrict__ W2, const float* __restrict__ b2,
                     const float* __restrict__ g2, const float* __restrict__ be2,
                     const float* __restrict__ W3, const float* __restrict__ b3,
                     float* __restrict__ out, int E)
{
    extern __shared__ float smem[];
    float* w1s  = smem + OFF_W1;
    float* w2s  = smem + OFF_W2;
    float* w3s  = smem + OFF_P;
    float* b1s  = smem + OFF_P + 64;
    float* g1s  = smem + OFF_P + 128;
    float* be1s = smem + OFF_P + 192;
    float* b2s  = smem + OFF_P + 256;
    float* g2s  = smem + OFF_P + 320;
    float* be2s = smem + OFF_P + 384;
    float* xs   = smem + OFF_X;              // [128][KD1] duplicated input (pairs)
    float* hs   = xs;                        // reuse: [128][HP]   (8704 floats)
    float* x2   = xs + TILE_E * HP;          // reuse: [128][KD2]  (19456 floats) disjoint from hs

    const int t = threadIdx.x;

    for (int i = t; i < 144 * 64; i += THREADS) w1s[i] = W1[i];
    for (int i = t; i < 64 * 64;  i += THREADS) w2s[i] = W2[i];
    if (t < 64) {
        w3s[t] = W3[t];
        b1s[t] = b1[t];  g1s[t] = g1[t];  be1s[t] = be1[t];
        b2s[t] = b2[t];  g2s[t] = g2[t];  be2s[t] = be2[t];
    }
    const float b3v = b3[0];
    __syncthreads();

    // GEMM thread mapping: 32 edge-groups (4 edges) x 8 col-groups (8 cols)
    const int eg = t >> 3;
    const int cg = t & 7;
    const int e0 = eg * 4;
    const int j0 = cg * 8;
    const int aswz = (eg & 3) * 8;           // bank swizzle for a-operand rows
    // gather / LN mapping: 2 threads per edge row
    const int el   = t >> 1;
    const int half = t & 1;

    const int ntiles = (E + TILE_E - 1) / TILE_E;
    for (int tile = blockIdx.x; tile < ntiles; tile += gridDim.x) {
        const int ebase = tile * TILE_E;
        const int ge = ebase + el;

        // ---------------- gather (duplicated pairs, row-major) ----------------
        {
            float* xrow = xs + el * KD1 + ((el >> 2) & 3) * 8;
            if (ge < E) {
                if (half == 0) {
                    const float4* s4 = (const float4*)(nf + (size_t)eidx[ge] * 64);
                    #pragma unroll
                    for (int q = 0; q < 16; q++) st_dup(xrow + 8 * q, s4[q]);          // k=4q
                    const float4* d4 = (const float4*)(nf + (size_t)eidx[E + ge] * 64);
                    #pragma unroll
                    for (int q = 0; q < 2; q++)  st_dup(xrow + 128 + 8 * q, d4[q]);    // k=64+4q
                } else {
                    const float4* d4 = (const float4*)(nf + (size_t)eidx[E + ge] * 64);
                    #pragma unroll
                    for (int q = 2; q < 16; q++) st_dup(xrow + 128 + 8 * q, d4[q]);    // k=64+4q
                    const float4* a4 = (const float4*)(eattr + (size_t)ge * 16);
                    #pragma unroll
                    for (int q = 0; q < 4; q++)  st_dup(xrow + 256 + 8 * q, a4[q]);    // k=128+4q
                }
            } else {
                float4 z = make_float4(0.f, 0.f, 0.f, 0.f);
                #pragma unroll
                for (int q = 0; q < 18; q++) st_dup(xrow + half * 144 + 8 * q, z);
            }
        }
        __syncthreads();

        // ---------------- GEMM1: h = x @ W1 (f32x2, col-pairs) ----------------
        ull c[16];
        #pragma unroll
        for (int i = 0; i < 16; i++) c[i] = 0ULL;
        {
            const float* arow = xs + e0 * KD1 + aswz;
            const float* brow = w1s + j0;
            #pragma unroll 4
            for (int k = 0; k < 144; k++) {
                ull a0 = ld64s(arow + 2 * k);
                ull a1 = ld64s(arow + KD1 + 2 * k);
                ull a2 = ld64s(arow + 2 * KD1 + 2 * k);
                ull a3 = ld64s(arow + 3 * KD1 + 2 * k);
                const float* bk = brow + k * 64;
                ull bb0 = ld64s(bk);
                ull bb1 = ld64s(bk + 2);
                ull bb2 = ld64s(bk + 4);
                ull bb3 = ld64s(bk + 6);
                c[0]  = ffma2(a0, bb0, c[0]);  c[1]  = ffma2(a0, bb1, c[1]);
                c[2]  = ffma2(a0, bb2, c[2]);  c[3]  = ffma2(a0, bb3, c[3]);
                c[4]  = ffma2(a1, bb0, c[4]);  c[5]  = ffma2(a1, bb1, c[5]);
                c[6]  = ffma2(a1, bb2, c[6]);  c[7]  = ffma2(a1, bb3, c[7]);
                c[8]  = ffma2(a2, bb0, c[8]);  c[9]  = ffma2(a2, bb1, c[9]);
                c[10] = ffma2(a2, bb2, c[10]); c[11] = ffma2(a2, bb3, c[11]);
                c[12] = ffma2(a3, bb0, c[12]); c[13] = ffma2(a3, bb1, c[13]);
                c[14] = ffma2(a3, bb2, c[14]); c[15] = ffma2(a3, bb3, c[15]);
            }
        }
        __syncthreads();   // xs fully consumed; hs (aliased) may now be written

        {
            float4 bb0 = *(const float4*)(b1s + j0);
            float4 bb1 = *(const float4*)(b1s + j0 + 4);
            #pragma unroll
            for (int i = 0; i < 4; i++) {
                float2 p0 = u2f2(c[i * 4 + 0]);
                float2 p1 = u2f2(c[i * 4 + 1]);
                float2 p2 = u2f2(c[i * 4 + 2]);
                float2 p3 = u2f2(c[i * 4 + 3]);
                float* hr = hs + (e0 + i) * HP + j0;
                *(float4*)(hr)     = make_float4(p0.x + bb0.x, p0.y + bb0.y, p1.x + bb0.z, p1.y + bb0.w);
                *(float4*)(hr + 4) = make_float4(p2.x + bb1.x, p2.y + bb1.y, p3.x + bb1.z, p3.y + bb1.w);
            }
        }
        __syncthreads();

        // ---------------- LN1 + leaky -> x2 (duplicated pairs) ----------------
        {
            const float* hr = hs + el * HP + half * 32;
            float v[32];
            float s = 0.f, sq = 0.f;
            #pragma unroll
            for (int q = 0; q < 8; q++) {
                float4 w = *(const float4*)(hr + 4 * q);
                v[4*q+0] = w.x; v[4*q+1] = w.y; v[4*q+2] = w.z; v[4*q+3] = w.w;
            }
            #pragma unroll
            for (int i = 0; i < 32; i++) { s += v[i]; sq += v[i] * v[i]; }
            s  += __shfl_xor_sync(0xffffffffu, s, 1);
            sq += __shfl_xor_sync(0xffffffffu, sq, 1);
            const float mu = s * (1.0f / 64.0f);
            const float var = sq * (1.0f / 64.0f) - mu * mu;
            const float rstd = rsqrtf(var + 1e-5f);
            float* x2row = x2 + el * KD2 + ((el >> 2) & 3) * 8 + half * 64;
            #pragma unroll
            for (int q = 0; q < 8; q++) {
                int jb = half * 32 + 4 * q;
                float4 gg = *(const float4*)(g1s + jb);
                float4 ee = *(const float4*)(be1s + jb);
                float4 y;
                y.x = (v[4*q+0] - mu) * rstd * gg.x + ee.x;  y.x = (y.x >= 0.f) ? y.x : 0.1f * y.x;
                y.y = (v[4*q+1] - mu) * rstd * gg.y + ee.y;  y.y = (y.y >= 0.f) ? y.y : 0.1f * y.y;
                y.z = (v[4*q+2] - mu) * rstd * gg.z + ee.z;  y.z = (y.z >= 0.f) ? y.z : 0.1f * y.z;
                y.w = (v[4*q+3] - mu) * rstd * gg.w + ee.w;  y.w = (y.w >= 0.f) ? y.w : 0.1f * y.w;
                st_dup(x2row + 8 * q, y);
            }
        }
        __syncthreads();

        // ---------------- GEMM2: h2 = h1 @ W2 ----------------
        #pragma unroll
        for (int i = 0; i < 16; i++) c[i] = 0ULL;
        {
            const float* arow = x2 + e0 * KD2 + aswz;
            const float* brow = w2s + j0;
            #pragma unroll 4
            for (int k = 0; k < 64; k++) {
                ull a0 = ld64s(arow + 2 * k);
                ull a1 = ld64s(arow + KD2 + 2 * k);
                ull a2 = ld64s(arow + 2 * KD2 + 2 * k);
                ull a3 = ld64s(arow + 3 * KD2 + 2 * k);
                const float* bk = brow + k * 64;
                ull bb0 = ld64s(bk);
                ull bb1 = ld64s(bk + 2);
                ull bb2 = ld64s(bk + 4);
                ull bb3 = ld64s(bk + 6);
                c[0]  = ffma2(a0, bb0, c[0]);  c[1]  = ffma2(a0, bb1, c[1]);
                c[2]  = ffma2(a0, bb2, c[2]);  c[3]  = ffma2(a0, bb3, c[3]);
                c[4]  = ffma2(a1, bb0, c[4]);  c[5]  = ffma2(a1, bb1, c[5]);
                c[6]  = ffma2(a1, bb2, c[6]);  c[7]  = ffma2(a1, bb3, c[7]);
                c[8]  = ffma2(a2, bb0, c[8]);  c[9]  = ffma2(a2, bb1, c[9]);
                c[10] = ffma2(a2, bb2, c[10]); c[11] = ffma2(a2, bb3, c[11]);
                c[12] = ffma2(a3, bb0, c[12]); c[13] = ffma2(a3, bb1, c[13]);
                c[14] = ffma2(a3, bb2, c[14]); c[15] = ffma2(a3, bb3, c[15]);
            }
        }
        // h2 store: reads were from x2 (disjoint from hs) — no barrier needed first
        {
            float4 bb0 = *(const float4*)(b2s + j0);
            float4 bb1 = *(const float4*)(b2s + j0 + 4);
            #pragma unroll
            for (int i = 0; i < 4; i++) {
                float2 p0 = u2f2(c[i * 4 + 0]);
                float2 p1 = u2f2(c[i * 4 + 1]);
                float2 p2 = u2f2(c[i * 4 + 2]);
                float2 p3 = u2f2(c[i * 4 + 3]);
                float* hr = hs + (e0 + i) * HP + j0;
                *(float4*)(hr)     = make_float4(p0.x + bb0.x, p0.y + bb0.y, p1.x + bb0.z, p1.y + bb0.w);
                *(float4*)(hr + 4) = make_float4(p2.x + bb1.x, p2.y + bb1.y, p3.x + bb1.z, p3.y + bb1.w);
            }
        }
        __syncthreads();

        // ---------------- LN2 + leaky + dot(W3) -> out ----------------
        {
            const float* hr = hs + el * HP + half * 32;
            float v[32];
            float s = 0.f, sq = 0.f;
            #pragma unroll
            for (int q = 0; q < 8; q++) {
                float4 w = *(const float4*)(hr + 4 * q);
                v[4*q+0] = w.x; v[4*q+1] = w.y; v[4*q+2] = w.z; v[4*q+3] = w.w;
            }
            #pragma unroll
            for (int i = 0; i < 32; i++) { s += v[i]; sq += v[i] * v[i]; }
            s  += __shfl_xor_sync(0xffffffffu, s, 1);
            sq += __shfl_xor_sync(0xffffffffu, sq, 1);
            const float mu = s * (1.0f / 64.0f);
            const float var = sq * (1.0f / 64.0f) - mu * mu;
            const float rstd = rsqrtf(var + 1e-5f);
            float acc = 0.f;
            #pragma unroll
            for (int q = 0; q < 8; q++) {
                int jb = half * 32 + 4 * q;
                float4 gg = *(const float4*)(g2s + jb);
                float4 ee = *(const float4*)(be2s + jb);
                float4 ww = *(const float4*)(w3s + jb);
                float y0 = (v[4*q+0] - mu) * rstd * gg.x + ee.x;  y0 = (y0 >= 0.f) ? y0 : 0.1f * y0;
                float y1 = (v[4*q+1] - mu) * rstd * gg.y + ee.y;  y1 = (y1 >= 0.f) ? y1 : 0.1f * y1;
                float y2 = (v[4*q+2] - mu) * rstd * gg.z + ee.z;  y2 = (y2 >= 0.f) ? y2 : 0.1f * y2;
                float y3 = (v[4*q+3] - mu) * rstd * gg.w + ee.w;  y3 = (y3 >= 0.f) ? y3 : 0.1f * y3;
                acc += y0 * ww.x + y1 * ww.y + y2 * ww.z + y3 * ww.w;
            }
            acc += __shfl_xor_sync(0xffffffffu, acc, 1);
            if (half == 0 && ge < E)
                out[ge] = acc + b3v;
        }
        __syncthreads();   // before next tile's gather overwrites xs/hs/x2
    }
}

extern "C" void kernel_launch(void* const* d_in, const int* in_sizes, int n_in,
                              void* d_out, int out_size) {
    const float* nf    = (const float*)d_in[0];
    const int*   eidx  = (const int*)d_in[1];
    const float* eattr = (const float*)d_in[2];
    const float* W1 = (const float*)d_in[3];
    const float* b1 = (const float*)d_in[4];
    const float* g1 = (const float*)d_in[5];
    const float* be1= (const float*)d_in[6];
    const float* W2 = (const float*)d_in[7];
    const float* b2 = (const float*)d_in[8];
    const float* g2 = (const float*)d_in[9];
    const float* be2= (const float*)d_in[10];
    const float* W3 = (const float*)d_in[11];
    const float* b3 = (const float*)d_in[12];
    float* out = (float*)d_out;
    const int E = out_size;

    cudaFuncSetAttribute(edge_mlp_kernel,
                         cudaFuncAttributeMaxDynamicSharedMemorySize,
                         SMEM_FLOATS * sizeof(float));

    int ntiles = (E + TILE_E - 1) / TILE_E;
    int grid = ntiles < 148 ? ntiles : 148;   // persistent, 1 block/SM
    edge_mlp_kernel<<<grid, THREADS, SMEM_FLOATS * sizeof(float)>>>(
        nf, eidx, eattr, W1, b1, g1, be1, W2, b2, g2, be2, W3, b3, out, E);
}

// round 7
// speedup vs baseline: 3.2898x; 3.2898x over previous
#include <cuda_runtime.h>
#include <cuda_bf16.h>
#include <cstdint>

typedef uint32_t u32; typedef uint64_t u64;

#define THREADS 256
#define TILE_E  128

// ---- smem layout (bytes) ----
// B1 fragment-packed: 18 kchunks (9 hi, 9 lo) x 8 nfrag x 32 lanes x 8B
#define OFF_B1  0
#define OFF_B2  36864            // 8 kchunks x 8 x 32 x 8
#define OFF_PAR 53248            // b1,g1,be1,b2,g2,be2,w3: 7*64 f32
#define OFF_A1  55296            // 18 chunk-tiles [128 rows][32B], XOR-swizzled
#define OFF_A2  129024           // 8 chunk-tiles  [128 rows][32B]
#define SMEM_BYTES 161792

static __device__ __forceinline__ u32 s2u(const void* p) {
    u32 a; asm("{ .reg .u64 t; cvta.to.shared.u64 t, %1; cvt.u32.u64 %0, t; }" : "=r"(a) : "l"(p));
    return a;
}
// split (f0,f1) -> bf16x2 hi + bf16x2 residual
static __device__ __forceinline__ u32 pack2(float f0, float f1, u32& lo) {
    u32 hi;
    asm("cvt.rn.bf16x2.f32 %0, %1, %2;" : "=r"(hi) : "f"(f1), "f"(f0));
    float h0 = __uint_as_float(hi << 16);
    float h1 = __uint_as_float(hi & 0xFFFF0000u);
    asm("cvt.rn.bf16x2.f32 %0, %1, %2;" : "=r"(lo) : "f"(f1 - h1), "f"(f0 - h0));
    return hi;
}
#define LDSM4(a0,a1,a2,a3,addr) \
    asm volatile("ldmatrix.sync.aligned.m8n8.x4.shared.b16 {%0,%1,%2,%3}, [%4];" \
        : "=r"(a0),"=r"(a1),"=r"(a2),"=r"(a3) : "r"(addr))
#define LDSB(b0,b1,addr) \
    asm volatile("ld.shared.v2.b32 {%0,%1}, [%2];" : "=r"(b0),"=r"(b1) : "r"(addr))
#define MMA(Cv,a0,a1,a2,a3,b0,b1) \
    asm volatile("mma.sync.aligned.m16n8k16.row.col.f32.bf16.bf16.f32 " \
        "{%0,%1,%2,%3}, {%4,%5,%6,%7}, {%8,%9}, {%0,%1,%2,%3};" \
        : "+f"((Cv)[0]),"+f"((Cv)[1]),"+f"((Cv)[2]),"+f"((Cv)[3]) \
        : "r"(a0),"r"(a1),"r"(a2),"r"(a3),"r"(b0),"r"(b1))

__global__ __launch_bounds__(THREADS)
void edge_mlp_mma(const float* __restrict__ nf,
                  const int* __restrict__ eidx,
                  const float* __restrict__ eattr,
                  const float* __restrict__ W1, const float* __restrict__ b1,
                  const float* __restrict__ g1, const float* __restrict__ be1,
                  const float* __restrict__ W2, const float* __restrict__ b2,
                  const float* __restrict__ g2, const float* __restrict__ be2,
                  const float* __restrict__ W3, const float* __restrict__ b3,
                  float* __restrict__ out, int E)
{
    extern __shared__ char smem[];
    const u32 sb = s2u(smem);
    const int t = threadIdx.x, wid = t >> 5, lid = t & 31;

    // ---------- weight prep: B1/B2 in mma-fragment order, bf16 hi/lo ----------
    for (int i = t; i < 18 * 8 * 32; i += THREADS) {
        int c = i >> 8, rem = i & 255, n = rem >> 5, l = rem & 31;
        int kb = 16 * (c % 9) + 2 * (l & 3), col = 8 * n + (l >> 2);
        float w0 = W1[(kb)     * 64 + col], w1 = W1[(kb + 1) * 64 + col];
        float w2 = W1[(kb + 8) * 64 + col], w3v = W1[(kb + 9) * 64 + col];
        u32 l0, l1, h0 = pack2(w0, w1, l0), h1 = pack2(w2, w3v, l1);
        uint2 v = (c < 9) ? make_uint2(h0, h1) : make_uint2(l0, l1);
        *(uint2*)(smem + OFF_B1 + i * 8) = v;
    }
    for (int i = t; i < 8 * 8 * 32; i += THREADS) {
        int c = i >> 8, rem = i & 255, n = rem >> 5, l = rem & 31;
        int kb = 16 * (c & 3) + 2 * (l & 3), col = 8 * n + (l >> 2);
        float w0 = W2[(kb)     * 64 + col], w1 = W2[(kb + 1) * 64 + col];
        float w2 = W2[(kb + 8) * 64 + col], w3v = W2[(kb + 9) * 64 + col];
        u32 l0, l1, h0 = pack2(w0, w1, l0), h1 = pack2(w2, w3v, l1);
        uint2 v = (c < 4) ? make_uint2(h0, h1) : make_uint2(l0, l1);
        *(uint2*)(smem + OFF_B2 + i * 8) = v;
    }
    float* par = (float*)(smem + OFF_PAR);
    if (t < 64) {
        par[t]       = b1[t];  par[64 + t]  = g1[t];  par[128 + t] = be1[t];
        par[192 + t] = b2[t];  par[256 + t] = g2[t];  par[320 + t] = be2[t];
        par[384 + t] = W3[t];
    }
    const float b3v = b3[0];
    __syncthreads();

    // ---------- per-lane constants ----------
    const int wr0 = wid * 16;
    // ldmatrix addressing (A chunk tiles: [128 rows][32B], half-XOR swizzle)
    const int lrow = wr0 + (lid & 15), lhalf = lid >> 4;
    const u32 lm_off = (u32)(lrow * 32 + (((lhalf ^ ((lrow >> 2) & 1))) << 4));
    const u32 boff = (u32)(lid * 8);
    // epilogue rows/cols
    const int rA = wr0 + (lid >> 2), rB = rA + 8, jb = 2 * (lid & 3);
    const int swA = (rA >> 2) & 1, swB = (rB >> 2) & 1;
    // gather mapping: 2 lanes per edge row
    const int grow = wr0 + (lid >> 1), ghalf = lid & 1;
    const int grsw = (grow >> 2) & 1;

    const int ntiles = (E + TILE_E - 1) / TILE_E;
    for (int tile = blockIdx.x; tile < ntiles; tile += gridDim.x) {
        const int ebase = tile * TILE_E;
        const int ge = ebase + grow;

        // -------- gather: LDG + bf16 split + swizzled STS into A1 --------
        if (ge < E) {
            if (ghalf == 0) {
                const float4* s4 = (const float4*)(nf + (size_t)eidx[ge] * 64);
                #pragma unroll
                for (int q = 0; q < 16; q++) {
                    float4 f = s4[q];
                    u32 l0, l1, h0 = pack2(f.x, f.y, l0), h1 = pack2(f.z, f.w, l1);
                    u32 base = OFF_A1 + (u32)((q >> 2) * 4096) + grow * 32
                             + ((((q >> 1) & 1) ^ grsw) << 4) + ((q & 1) << 3);
                    *(uint2*)(smem + base)            = make_uint2(h0, h1);
                    *(uint2*)(smem + base + 9 * 4096) = make_uint2(l0, l1);
                }
            } else {
                const float4* d4 = (const float4*)(nf + (size_t)eidx[E + ge] * 64);
                #pragma unroll
                for (int q = 0; q < 16; q++) {
                    float4 f = d4[q];
                    u32 l0, l1, h0 = pack2(f.x, f.y, l0), h1 = pack2(f.z, f.w, l1);
                    u32 base = OFF_A1 + (u32)((4 + (q >> 2)) * 4096) + grow * 32
                             + ((((q >> 1) & 1) ^ grsw) << 4) + ((q & 1) << 3);
                    *(uint2*)(smem + base)            = make_uint2(h0, h1);
                    *(uint2*)(smem + base + 9 * 4096) = make_uint2(l0, l1);
                }
                const float4* a4 = (const float4*)(eattr + (size_t)ge * 16);
                #pragma unroll
                for (int q = 0; q < 4; q++) {
                    float4 f = a4[q];
                    u32 l0, l1, h0 = pack2(f.x, f.y, l0), h1 = pack2(f.z, f.w, l1);
                    u32 base = OFF_A1 + (u32)(8 * 4096) + grow * 32
                             + ((((q >> 1) & 1) ^ grsw) << 4) + ((q & 1) << 3);
                    *(uint2*)(smem + base)            = make_uint2(h0, h1);
                    *(uint2*)(smem + base + 9 * 4096) = make_uint2(l0, l1);
                }
            }
        }
        __syncwarp();

        // -------- GEMM1: 27 kchunks (hi*hi 9, lo*hi 9, hi*lo 9) --------
        float C[8][4];
        #pragma unroll
        for (int n = 0; n < 8; n++)
            C[n][0] = C[n][1] = C[n][2] = C[n][3] = 0.f;
        #pragma unroll
        for (int c = 0; c < 27; c++) {
            const int ac = (c < 18) ? c : c - 18;
            const int bc = (c < 9)  ? c : c - 9;
            u32 a0, a1, a2, a3;
            LDSM4(a0, a1, a2, a3, sb + OFF_A1 + (u32)(ac * 4096) + lm_off);
            #pragma unroll
            for (int n = 0; n < 8; n++) {
                u32 b0, b1;
                LDSB(b0, b1, sb + OFF_B1 + (u32)(((bc * 8 + n) << 8)) + boff);
                MMA(C[n], a0, a1, a2, a3, b0, b1);
            }
        }

        // -------- epilogue 1: bias + LN + leaky -> A2 (bf16 hi/lo) --------
        {
            float vA[16], vB[16];
            float sA = 0.f, qA = 0.f, sB = 0.f, qB = 0.f;
            #pragma unroll
            for (int n = 0; n < 8; n++) {
                int j = 8 * n + jb;
                float t0 = C[n][0] + par[j], t1 = C[n][1] + par[j + 1];
                float t2 = C[n][2] + par[j], t3 = C[n][3] + par[j + 1];
                vA[2*n] = t0; vA[2*n+1] = t1; vB[2*n] = t2; vB[2*n+1] = t3;
                sA += t0 + t1; qA += t0 * t0 + t1 * t1;
                sB += t2 + t3; qB += t2 * t2 + t3 * t3;
            }
            sA += __shfl_xor_sync(~0u, sA, 1); qA += __shfl_xor_sync(~0u, qA, 1);
            sB += __shfl_xor_sync(~0u, sB, 1); qB += __shfl_xor_sync(~0u, qB, 1);
            sA += __shfl_xor_sync(~0u, sA, 2); qA += __shfl_xor_sync(~0u, qA, 2);
            sB += __shfl_xor_sync(~0u, sB, 2); qB += __shfl_xor_sync(~0u, qB, 2);
            float muA = sA * (1.f/64.f), muB = sB * (1.f/64.f);
            float rsA = rsqrtf(qA * (1.f/64.f) - muA * muA + 1e-5f);
            float rsB = rsqrtf(qB * (1.f/64.f) - muB * muB + 1e-5f);
            #pragma unroll
            for (int n = 0; n < 8; n++) {
                int j = 8 * n + jb;
                float g0 = par[64 + j], g1v = par[64 + j + 1];
                float e0 = par[128 + j], e1 = par[128 + j + 1];
                float z0 = (vA[2*n]   - muA) * rsA * g0 + e0;
                float z1 = (vA[2*n+1] - muA) * rsA * g1v + e1;
                z0 = (z0 >= 0.f) ? z0 : 0.1f * z0;
                z1 = (z1 >= 0.f) ? z1 : 0.1f * z1;
                u32 lo, hi = pack2(z0, z1, lo);
                u32 ad = OFF_A2 + (u32)((n >> 1) * 4096) + rA * 32
                       + (((n & 1) ^ swA) << 4) + jb * 2;
                *(u32*)(smem + ad) = hi;
                *(u32*)(smem + ad + 4 * 4096) = lo;
                z0 = (vB[2*n]   - muB) * rsB * g0 + e0;
                z1 = (vB[2*n+1] - muB) * rsB * g1v + e1;
                z0 = (z0 >= 0.f) ? z0 : 0.1f * z0;
                z1 = (z1 >= 0.f) ? z1 : 0.1f * z1;
                hi = pack2(z0, z1, lo);
                ad = OFF_A2 + (u32)((n >> 1) * 4096) + rB * 32
                   + (((n & 1) ^ swB) << 4) + jb * 2;
                *(u32*)(smem + ad) = hi;
                *(u32*)(smem + ad + 4 * 4096) = lo;
            }
        }
        __syncwarp();

        // -------- GEMM2: 12 kchunks (hi*hi 4, lo*hi 4, hi*lo 4) --------
        #pragma unroll
        for (int n = 0; n < 8; n++)
            C[n][0] = C[n][1] = C[n][2] = C[n][3] = 0.f;
        #pragma unroll
        for (int c = 0; c < 12; c++) {
            const int ac = (c < 8) ? c : c - 8;
            const int bc = (c < 4) ? c : c - 4;
            u32 a0, a1, a2, a3;
            LDSM4(a0, a1, a2, a3, sb + OFF_A2 + (u32)(ac * 4096) + lm_off);
            #pragma unroll
            for (int n = 0; n < 8; n++) {
                u32 b0, b1;
                LDSB(b0, b1, sb + OFF_B2 + (u32)(((bc * 8 + n) << 8)) + boff);
                MMA(C[n], a0, a1, a2, a3, b0, b1);
            }
        }

        // -------- epilogue 2: bias + LN + leaky + dot(W3) -> out --------
        {
            float vA[16], vB[16];
            float sA = 0.f, qA = 0.f, sB = 0.f, qB = 0.f;
            #pragma unroll
            for (int n = 0; n < 8; n++) {
                int j = 8 * n + jb;
                float t0 = C[n][0] + par[192 + j], t1 = C[n][1] + par[192 + j + 1];
                float t2 = C[n][2] + par[192 + j], t3 = C[n][3] + par[192 + j + 1];
                vA[2*n] = t0; vA[2*n+1] = t1; vB[2*n] = t2; vB[2*n+1] = t3;
                sA += t0 + t1; qA += t0 * t0 + t1 * t1;
                sB += t2 + t3; qB += t2 * t2 + t3 * t3;
            }
            sA += __shfl_xor_sync(~0u, sA, 1); qA += __shfl_xor_sync(~0u, qA, 1);
            sB += __shfl_xor_sync(~0u, sB, 1); qB += __shfl_xor_sync(~0u, qB, 1);
            sA += __shfl_xor_sync(~0u, sA, 2); qA += __shfl_xor_sync(~0u, qA, 2);
            sB += __shfl_xor_sync(~0u, sB, 2); qB += __shfl_xor_sync(~0u, qB, 2);
            float muA = sA * (1.f/64.f), muB = sB * (1.f/64.f);
            float rsA = rsqrtf(qA * (1.f/64.f) - muA * muA + 1e-5f);
            float rsB = rsqrtf(qB * (1.f/64.f) - muB * muB + 1e-5f);
            float aA = 0.f, aB = 0.f;
            #pragma unroll
            for (int n = 0; n < 8; n++) {
                int j = 8 * n + jb;
                float g0 = par[256 + j], g1v = par[256 + j + 1];
                float e0 = par[320 + j], e1 = par[320 + j + 1];
                float w0 = par[384 + j], w1 = par[384 + j + 1];
                float z0 = (vA[2*n]   - muA) * rsA * g0 + e0;
                float z1 = (vA[2*n+1] - muA) * rsA * g1v + e1;
                z0 = (z0 >= 0.f) ? z0 : 0.1f * z0;
                z1 = (z1 >= 0.f) ? z1 : 0.1f * z1;
                aA += z0 * w0 + z1 * w1;
                z0 = (vB[2*n]   - muB) * rsB * g0 + e0;
                z1 = (vB[2*n+1] - muB) * rsB * g1v + e1;
                z0 = (z0 >= 0.f) ? z0 : 0.1f * z0;
                z1 = (z1 >= 0.f) ? z1 : 0.1f * z1;
                aB += z0 * w0 + z1 * w1;
            }
            aA += __shfl_xor_sync(~0u, aA, 1);
            aB += __shfl_xor_sync(~0u, aB, 1);
            aA += __shfl_xor_sync(~0u, aA, 2);
            aB += __shfl_xor_sync(~0u, aB, 2);
            if ((lid & 3) == 0) {
                if (ebase + rA < E) out[ebase + rA] = aA + b3v;
                if (ebase + rB < E) out[ebase + rB] = aB + b3v;
            }
        }
        __syncwarp();   // A1/A2 rows reusable next tile (same warp only)
    }
}

extern "C" void kernel_launch(void* const* d_in, const int* in_sizes, int n_in,
                              void* d_out, int out_size) {
    const float* nf    = (const float*)d_in[0];
    const int*   eidx  = (const int*)d_in[1];
    const float* eattr = (const float*)d_in[2];
    const float* W1 = (const float*)d_in[3];
    const float* b1 = (const float*)d_in[4];
    const float* g1 = (const float*)d_in[5];
    const float* be1= (const float*)d_in[6];
    const float* W2 = (const float*)d_in[7];
    const float* b2 = (const float*)d_in[8];
    const float* g2 = (const float*)d_in[9];
    const float* be2= (const float*)d_in[10];
    const float* W3 = (const float*)d_in[11];
    const float* b3 = (const float*)d_in[12];
    float* out = (float*)d_out;
    const int E = out_size;

    cudaFuncSetAttribute(edge_mlp_mma,
                         cudaFuncAttributeMaxDynamicSharedMemorySize, SMEM_BYTES);

    int ntiles = (E + TILE_E - 1) / TILE_E;
    int grid = ntiles < 148 ? ntiles : 148;   // persistent, 1 CTA/SM
    edge_mlp_mma<<<grid, THREADS, SMEM_BYTES>>>(
        nf, eidx, eattr, W1, b1, g1, be1, W2, b2, g2, be2, W3, b3, out, E);
}

// round 8
// speedup vs baseline: 4.1129x; 1.2502x over previous
#include <cuda_runtime.h>
#include <cuda_bf16.h>
#include <cstdint>

typedef uint32_t u32; typedef uint64_t u64;

#define THREADS 256
#define TILE_E  128
#define MAX_NODES 50000

__device__ float g_proj[MAX_NODES * 128];   // [node][0:64]=nf@W1a+b1, [64:128]=nf@W1b

// ---------------- edge-kernel smem (bytes) ----------------
#define OFF_B1C 0            // eattr weights: 2 sets (hi,lo) x 8n x 32 x 8B = 4096
#define OFF_B2  4096         // 8 sets x 8n x 32 x 8B = 16384
#define OFF_PAR 20480        // g1,be1,b2,g2,be2,w3 : 6*64 f32 = 1536
#define OFF_A1  22528        // eattr A: hi 4096 + lo 4096
#define OFF_A2  30720        // 8 x 4096
#define OFF_H1  63488        // h1pre: 128 x 72 f32 = 36864
#define SMEM_EDGE 100352

// ---------------- proj-kernel smem ----------------
#define OFF_PB   0           // 8 sets x 16n x 32 x 8B = 32768
#define OFF_PA   32768       // 8 tiles x 4096
#define OFF_PBIAS 65536      // 64 f32
#define SMEM_PROJ 65792

static __device__ __forceinline__ u32 s2u(const void* p) {
    u32 a; asm("{ .reg .u64 t; cvta.to.shared.u64 t, %1; cvt.u32.u64 %0, t; }" : "=r"(a) : "l"(p));
    return a;
}
static __device__ __forceinline__ u32 pack2(float f0, float f1, u32& lo) {
    u32 hi;
    asm("cvt.rn.bf16x2.f32 %0, %1, %2;" : "=r"(hi) : "f"(f1), "f"(f0));
    float h0 = __uint_as_float(hi << 16);
    float h1 = __uint_as_float(hi & 0xFFFF0000u);
    asm("cvt.rn.bf16x2.f32 %0, %1, %2;" : "=r"(lo) : "f"(f1 - h1), "f"(f0 - h0));
    return hi;
}
#define LDSM4(a0,a1,a2,a3,addr) \
    asm volatile("ldmatrix.sync.aligned.m8n8.x4.shared.b16 {%0,%1,%2,%3}, [%4];" \
        : "=r"(a0),"=r"(a1),"=r"(a2),"=r"(a3) : "r"(addr))
#define LDSB(b0,b1,addr) \
    asm volatile("ld.shared.v2.b32 {%0,%1}, [%2];" : "=r"(b0),"=r"(b1) : "r"(addr))
#define MMA(Cv,a0,a1,a2,a3,b0,b1) \
    asm volatile("mma.sync.aligned.m16n8k16.row.col.f32.bf16.bf16.f32 " \
        "{%0,%1,%2,%3}, {%4,%5,%6,%7}, {%8,%9}, {%0,%1,%2,%3};" \
        : "+f"((Cv)[0]),"+f"((Cv)[1]),"+f"((Cv)[2]),"+f"((Cv)[3]) \
        : "r"(a0),"r"(a1),"r"(a2),"r"(a3),"r"(b0),"r"(b1))

// ================= proj kernel: P = [nf@W1a + b1 | nf@W1b] =================
__global__ __launch_bounds__(THREADS)
void proj_kernel(const float* __restrict__ nf,
                 const float* __restrict__ W1,
                 const float* __restrict__ b1, int nn)
{
    extern __shared__ char smem[];
    const u32 sb = s2u(smem);
    const int t = threadIdx.x, wid = t >> 5, lid = t & 31;

    // pack B: W1 rows 0..127 -> N=128 (cols 0..63 = W1a, 64..127 = W1b), bf16 hi/lo
    for (int i = t; i < 8 * 16 * 32; i += THREADS) {
        int c = i >> 9, n = (i >> 5) & 15, l = i & 31;
        int kb = 16 * (c & 3) + 2 * (l & 3);
        int col8 = 8 * n + (l >> 2);
        int base = (col8 < 64) ? 0 : 64;
        int col = col8 & 63;
        float w0 = W1[(base + kb)     * 64 + col], w1 = W1[(base + kb + 1) * 64 + col];
        float w2 = W1[(base + kb + 8) * 64 + col], w3v = W1[(base + kb + 9) * 64 + col];
        u32 l0, l1, h0 = pack2(w0, w1, l0), h1 = pack2(w2, w3v, l1);
        uint2 v = (c < 4) ? make_uint2(h0, h1) : make_uint2(l0, l1);
        *(uint2*)(smem + OFF_PB + i * 8) = v;
    }
    float* bias = (float*)(smem + OFF_PBIAS);
    if (t < 64) bias[t] = b1[t];
    __syncthreads();

    const int wr0 = wid * 16;
    const int lrow = wr0 + (lid & 15), lhalf = lid >> 4;
    const u32 lm_off = (u32)(lrow * 32 + ((lhalf ^ ((lrow >> 2) & 1)) << 4));
    const int rA = wr0 + (lid >> 2), rB = rA + 8, jb = 2 * (lid & 3);
    const int grow = wr0 + (lid >> 1), ghalf = lid & 1;
    const int grsw = (grow >> 2) & 1;

    const int nbase = blockIdx.x * 128;
    const int node = nbase + grow;

    // gather nf rows -> split bf16 -> A tiles (hi 0..3, lo 4..7)
    if (node < nn) {
        const float4* r4 = (const float4*)(nf + (size_t)node * 64 + ghalf * 32);
        #pragma unroll
        for (int q = 0; q < 8; q++) {
            float4 f = r4[q];
            u32 l0, l1, h0 = pack2(f.x, f.y, l0), h1 = pack2(f.z, f.w, l1);
            u32 base = OFF_PA + (u32)((2 * ghalf + (q >> 2)) * 4096) + grow * 32
                     + ((((q >> 1) & 1) ^ grsw) << 4) + ((q & 1) << 3);
            *(uint2*)(smem + base)            = make_uint2(h0, h1);
            *(uint2*)(smem + base + 4 * 4096) = make_uint2(l0, l1);
        }
    } else {
        #pragma unroll
        for (int q = 0; q < 8; q++) {
            u32 base = OFF_PA + (u32)((2 * ghalf + (q >> 2)) * 4096) + grow * 32
                     + ((((q >> 1) & 1) ^ grsw) << 4) + ((q & 1) << 3);
            *(uint2*)(smem + base)            = make_uint2(0u, 0u);
            *(uint2*)(smem + base + 4 * 4096) = make_uint2(0u, 0u);
        }
    }
    __syncwarp();

    float C[16][4];
    #pragma unroll
    for (int n = 0; n < 16; n++)
        C[n][0] = C[n][1] = C[n][2] = C[n][3] = 0.f;
    #pragma unroll
    for (int c = 0; c < 12; c++) {
        const int ac = (c < 8) ? c : c - 8;
        const int bc = (c < 4) ? c : c - 4;
        u32 a0, a1, a2, a3;
        LDSM4(a0, a1, a2, a3, sb + OFF_PA + (u32)(ac * 4096) + lm_off);
        #pragma unroll
        for (int n = 0; n < 16; n++) {
            u32 b0, b1v;
            LDSB(b0, b1v, sb + OFF_PB + (u32)((bc * 16 + n) * 256) + lid * 8);
            MMA(C[n], a0, a1, a2, a3, b0, b1v);
        }
    }

    const int nodeA = nbase + rA, nodeB = nbase + rB;
    #pragma unroll
    for (int n = 0; n < 16; n++) {
        int col = 8 * n + jb;
        float bb0 = (col < 64) ? bias[col] : 0.f;
        float bb1 = (col < 64) ? bias[col + 1] : 0.f;
        if (nodeA < nn)
            *(float2*)(g_proj + (size_t)nodeA * 128 + col) = make_float2(C[n][0] + bb0, C[n][1] + bb1);
        if (nodeB < nn)
            *(float2*)(g_proj + (size_t)nodeB * 128 + col) = make_float2(C[n][2] + bb0, C[n][3] + bb1);
    }
}

// ================= edge kernel =================
__global__ __launch_bounds__(THREADS)
void edge_mlp_mma(const int* __restrict__ eidx,
                  const float* __restrict__ eattr,
                  const float* __restrict__ W1,
                  const float* __restrict__ g1, const float* __restrict__ be1,
                  const float* __restrict__ W2, const float* __restrict__ b2,
                  const float* __restrict__ g2, const float* __restrict__ be2,
                  const float* __restrict__ W3, const float* __restrict__ b3,
                  float* __restrict__ out, int E)
{
    extern __shared__ char smem[];
    const u32 sb = s2u(smem);
    const int t = threadIdx.x, wid = t >> 5, lid = t & 31;

    // ---- B1c: W1 rows 128..143 (eattr block), fragment-packed hi/lo ----
    for (int i = t; i < 2 * 8 * 32; i += THREADS) {
        int c = i >> 8, n = (i >> 5) & 7, l = i & 31;
        int kb = 2 * (l & 3), col = 8 * n + (l >> 2);
        float w0 = W1[(128 + kb)     * 64 + col], w1 = W1[(128 + kb + 1) * 64 + col];
        float w2 = W1[(128 + kb + 8) * 64 + col], w3v = W1[(128 + kb + 9) * 64 + col];
        u32 l0, l1, h0 = pack2(w0, w1, l0), h1 = pack2(w2, w3v, l1);
        uint2 v = (c == 0) ? make_uint2(h0, h1) : make_uint2(l0, l1);
        *(uint2*)(smem + OFF_B1C + i * 8) = v;
    }
    // ---- B2: as in R7 ----
    for (int i = t; i < 8 * 8 * 32; i += THREADS) {
        int c = i >> 8, n = (i >> 5) & 7, l = i & 31;
        int kb = 16 * (c & 3) + 2 * (l & 3), col = 8 * n + (l >> 2);
        float w0 = W2[(kb)     * 64 + col], w1 = W2[(kb + 1) * 64 + col];
        float w2 = W2[(kb + 8) * 64 + col], w3v = W2[(kb + 9) * 64 + col];
        u32 l0, l1, h0 = pack2(w0, w1, l0), h1 = pack2(w2, w3v, l1);
        uint2 v = (c < 4) ? make_uint2(h0, h1) : make_uint2(l0, l1);
        *(uint2*)(smem + OFF_B2 + i * 8) = v;
    }
    float* par = (float*)(smem + OFF_PAR);
    if (t < 64) {
        par[t]       = g1[t];  par[64 + t]  = be1[t];
        par[128 + t] = b2[t];  par[192 + t] = g2[t];
        par[256 + t] = be2[t]; par[320 + t] = W3[t];
    }
    const float b3v = b3[0];
    __syncthreads();

    const int wr0 = wid * 16;
    const int lrow = wr0 + (lid & 15), lhalf = lid >> 4;
    const u32 lm_off = (u32)(lrow * 32 + ((lhalf ^ ((lrow >> 2) & 1)) << 4));
    const u32 boff = (u32)(lid * 8);
    const int rA = wr0 + (lid >> 2), rB = rA + 8, jb = 2 * (lid & 3);
    const int swA = (rA >> 2) & 1, swB = (rB >> 2) & 1;
    const int grow = wr0 + (lid >> 1), ghalf = lid & 1;
    const int grsw = (grow >> 2) & 1;

    const int ntiles = (E + TILE_E - 1) / TILE_E;
    for (int tile = blockIdx.x; tile < ntiles; tile += gridDim.x) {
        const int ebase = tile * TILE_E;
        const int ge = ebase + grow;

        // -------- gather: proj rows (fp32 add -> h1pre) + eattr split -> A1 --------
        if (ge < E) {
            const int s = eidx[ge], d = eidx[E + ge];
            const float4* pa = (const float4*)(g_proj + (size_t)s * 128 + ghalf * 32);
            const float4* pb = (const float4*)(g_proj + (size_t)d * 128 + 64 + ghalf * 32);
            float* hrow = (float*)(smem + OFF_H1) + grow * 72 + ghalf * 32;
            #pragma unroll
            for (int q = 0; q < 8; q++) {
                float4 a = pa[q], b = pb[q];
                *(float4*)(hrow + 4 * q) = make_float4(a.x + b.x, a.y + b.y, a.z + b.z, a.w + b.w);
            }
            if (ghalf == 0) {
                const float4* a4 = (const float4*)(eattr + (size_t)ge * 16);
                #pragma unroll
                for (int q = 0; q < 4; q++) {
                    float4 f = a4[q];
                    u32 l0, l1, h0 = pack2(f.x, f.y, l0), h1 = pack2(f.z, f.w, l1);
                    u32 base = OFF_A1 + grow * 32 + ((((q >> 1) & 1) ^ grsw) << 4) + ((q & 1) << 3);
                    *(uint2*)(smem + base)        = make_uint2(h0, h1);
                    *(uint2*)(smem + base + 4096) = make_uint2(l0, l1);
                }
            }
        }
        __syncwarp();

        // -------- GEMM1c: eattr @ W1c, 3 kchunk-combos --------
        float C[8][4];
        #pragma unroll
        for (int n = 0; n < 8; n++)
            C[n][0] = C[n][1] = C[n][2] = C[n][3] = 0.f;
        #pragma unroll
        for (int c = 0; c < 3; c++) {
            const u32 at = OFF_A1 + ((c == 1) ? 4096u : 0u);     // hi, lo, hi
            const u32 bt = OFF_B1C + ((c == 2) ? 2048u : 0u);    // hi, hi, lo
            u32 a0, a1, a2, a3;
            LDSM4(a0, a1, a2, a3, sb + at + lm_off);
            #pragma unroll
            for (int n = 0; n < 8; n++) {
                u32 b0, b1v;
                LDSB(b0, b1v, sb + bt + (u32)(n * 256) + boff);
                MMA(C[n], a0, a1, a2, a3, b0, b1v);
            }
        }

        // -------- epilogue 1: + proj(h1pre) + LN + leaky -> A2 --------
        {
            const float* h1 = (const float*)(smem + OFF_H1);
            float vA[16], vB[16];
            float sA = 0.f, qA = 0.f, sB = 0.f, qB = 0.f;
            #pragma unroll
            for (int n = 0; n < 8; n++) {
                int j = 8 * n + jb;
                float2 pA = *(const float2*)(h1 + rA * 72 + j);
                float2 pB = *(const float2*)(h1 + rB * 72 + j);
                float t0 = C[n][0] + pA.x, t1 = C[n][1] + pA.y;
                float t2 = C[n][2] + pB.x, t3 = C[n][3] + pB.y;
                vA[2*n] = t0; vA[2*n+1] = t1; vB[2*n] = t2; vB[2*n+1] = t3;
                sA += t0 + t1; qA += t0 * t0 + t1 * t1;
                sB += t2 + t3; qB += t2 * t2 + t3 * t3;
            }
            sA += __shfl_xor_sync(~0u, sA, 1); qA += __shfl_xor_sync(~0u, qA, 1);
            sB += __shfl_xor_sync(~0u, sB, 1); qB += __shfl_xor_sync(~0u, qB, 1);
            sA += __shfl_xor_sync(~0u, sA, 2); qA += __shfl_xor_sync(~0u, qA, 2);
            sB += __shfl_xor_sync(~0u, sB, 2); qB += __shfl_xor_sync(~0u, qB, 2);
            float muA = sA * (1.f/64.f), muB = sB * (1.f/64.f);
            float rsA = rsqrtf(qA * (1.f/64.f) - muA * muA + 1e-5f);
            float rsB = rsqrtf(qB * (1.f/64.f) - muB * muB + 1e-5f);
            #pragma unroll
            for (int n = 0; n < 8; n++) {
                int j = 8 * n + jb;
                float g0 = par[j], g1v = par[j + 1];
                float e0 = par[64 + j], e1 = par[64 + j + 1];
                float z0 = (vA[2*n]   - muA) * rsA * g0 + e0;
                float z1 = (vA[2*n+1] - muA) * rsA * g1v + e1;
                z0 = (z0 >= 0.f) ? z0 : 0.1f * z0;
                z1 = (z1 >= 0.f) ? z1 : 0.1f * z1;
                u32 lo, hi = pack2(z0, z1, lo);
                u32 ad = OFF_A2 + (u32)((n >> 1) * 4096) + rA * 32
                       + (((n & 1) ^ swA) << 4) + jb * 2;
                *(u32*)(smem + ad) = hi;
                *(u32*)(smem + ad + 4 * 4096) = lo;
                z0 = (vB[2*n]   - muB) * rsB * g0 + e0;
                z1 = (vB[2*n+1] - muB) * rsB * g1v + e1;
                z0 = (z0 >= 0.f) ? z0 : 0.1f * z0;
                z1 = (z1 >= 0.f) ? z1 : 0.1f * z1;
                hi = pack2(z0, z1, lo);
                ad = OFF_A2 + (u32)((n >> 1) * 4096) + rB * 32
                   + (((n & 1) ^ swB) << 4) + jb * 2;
                *(u32*)(smem + ad) = hi;
                *(u32*)(smem + ad + 4 * 4096) = lo;
            }
        }
        __syncwarp();

        // -------- GEMM2: 12 kchunk-combos --------
        #pragma unroll
        for (int n = 0; n < 8; n++)
            C[n][0] = C[n][1] = C[n][2] = C[n][3] = 0.f;
        #pragma unroll
        for (int c = 0; c < 12; c++) {
            const int ac = (c < 8) ? c : c - 8;
            const int bc = (c < 4) ? c : c - 4;
            u32 a0, a1, a2, a3;
            LDSM4(a0, a1, a2, a3, sb + OFF_A2 + (u32)(ac * 4096) + lm_off);
            #pragma unroll
            for (int n = 0; n < 8; n++) {
                u32 b0, b1v;
                LDSB(b0, b1v, sb + OFF_B2 + (u32)((bc * 8 + n) * 256) + boff);
                MMA(C[n], a0, a1, a2, a3, b0, b1v);
            }
        }

        // -------- epilogue 2: bias + LN + leaky + dot(W3) -> out --------
        {
            float vA[16], vB[16];
            float sA = 0.f, qA = 0.f, sB = 0.f, qB = 0.f;
            #pragma unroll
            for (int n = 0; n < 8; n++) {
                int j = 8 * n + jb;
                float t0 = C[n][0] + par[128 + j], t1 = C[n][1] + par[128 + j + 1];
                float t2 = C[n][2] + par[128 + j], t3 = C[n][3] + par[128 + j + 1];
                vA[2*n] = t0; vA[2*n+1] = t1; vB[2*n] = t2; vB[2*n+1] = t3;
                sA += t0 + t1; qA += t0 * t0 + t1 * t1;
                sB += t2 + t3; qB += t2 * t2 + t3 * t3;
            }
            sA += __shfl_xor_sync(~0u, sA, 1); qA += __shfl_xor_sync(~0u, qA, 1);
            sB += __shfl_xor_sync(~0u, sB, 1); qB += __shfl_xor_sync(~0u, qB, 1);
            sA += __shfl_xor_sync(~0u, sA, 2); qA += __shfl_xor_sync(~0u, qA, 2);
            sB += __shfl_xor_sync(~0u, sB, 2); qB += __shfl_xor_sync(~0u, qB, 2);
            float muA = sA * (1.f/64.f), muB = sB * (1.f/64.f);
            float rsA = rsqrtf(qA * (1.f/64.f) - muA * muA + 1e-5f);
            float rsB = rsqrtf(qB * (1.f/64.f) - muB * muB + 1e-5f);
            float aA = 0.f, aB = 0.f;
            #pragma unroll
            for (int n = 0; n < 8; n++) {
                int j = 8 * n + jb;
                float g0 = par[192 + j], g1v = par[192 + j + 1];
                float e0 = par[256 + j], e1 = par[256 + j + 1];
                float w0 = par[320 + j], w1 = par[320 + j + 1];
                float z0 = (vA[2*n]   - muA) * rsA * g0 + e0;
                float z1 = (vA[2*n+1] - muA) * rsA * g1v + e1;
                z0 = (z0 >= 0.f) ? z0 : 0.1f * z0;
                z1 = (z1 >= 0.f) ? z1 : 0.1f * z1;
                aA += z0 * w0 + z1 * w1;
                z0 = (vB[2*n]   - muB) * rsB * g0 + e0;
                z1 = (vB[2*n+1] - muB) * rsB * g1v + e1;
                z0 = (z0 >= 0.f) ? z0 : 0.1f * z0;
                z1 = (z1 >= 0.f) ? z1 : 0.1f * z1;
                aB += z0 * w0 + z1 * w1;
            }
            aA += __shfl_xor_sync(~0u, aA, 1);
            aB += __shfl_xor_sync(~0u, aB, 1);
            aA += __shfl_xor_sync(~0u, aA, 2);
            aB += __shfl_xor_sync(~0u, aB, 2);
            if ((lid & 3) == 0) {
                if (ebase + rA < E) out[ebase + rA] = aA + b3v;
                if (ebase + rB < E) out[ebase + rB] = aB + b3v;
            }
        }
        __syncwarp();
    }
}

extern "C" void kernel_launch(void* const* d_in, const int* in_sizes, int n_in,
                              void* d_out, int out_size) {
    const float* nf    = (const float*)d_in[0];
    const int*   eidx  = (const int*)d_in[1];
    const float* eattr = (const float*)d_in[2];
    const float* W1 = (const float*)d_in[3];
    const float* b1 = (const float*)d_in[4];
    const float* g1 = (const float*)d_in[5];
    const float* be1= (const float*)d_in[6];
    const float* W2 = (const float*)d_in[7];
    const float* b2 = (const float*)d_in[8];
    const float* g2 = (const float*)d_in[9];
    const float* be2= (const float*)d_in[10];
    const float* W3 = (const float*)d_in[11];
    const float* b3 = (const float*)d_in[12];
    float* out = (float*)d_out;
    const int E = out_size;
    const int nn = in_sizes[0] / 64;

    cudaFuncSetAttribute(proj_kernel,
                         cudaFuncAttributeMaxDynamicSharedMemorySize, SMEM_PROJ);
    cudaFuncSetAttribute(edge_mlp_mma,
                         cudaFuncAttributeMaxDynamicSharedMemorySize, SMEM_EDGE);

    int pblocks = (nn + 127) / 128;
    proj_kernel<<<pblocks, THREADS, SMEM_PROJ>>>(nf, W1, b1, nn);

    int ntiles = (E + TILE_E - 1) / TILE_E;
    int grid = ntiles < 148 ? ntiles : 148;
    edge_mlp_mma<<<grid, THREADS, SMEM_EDGE>>>(
        eidx, eattr, W1, g1, be1, W2, b2, g2, be2, W3, b3, out, E);
}